// round 14
// baseline (speedup 1.0000x reference)
#include <cuda_runtime.h>
#include <cuda_bf16.h>
#include <cstdint>

#define DIM   1024
#define NQ    10
#define NWIN  65472
#define NWPB  4092
#define NPAD  65536
#define NTILES  36

typedef unsigned long long ull;
typedef unsigned int uint;

// M^T hi/lo [j][d], and sign-folded M^T for Q = M^T Sigma M (bf16, qprep only)
__device__ __nv_bfloat16 g_Mth[DIM * DIM];
__device__ __nv_bfloat16 g_Mtl[DIM * DIM];
__device__ __nv_bfloat16 g_Msh[DIM * DIM];
__device__ __nv_bfloat16 g_Msl[DIM * DIM];
// folded Q int8 limbs (lower tiles, off-diag x2): F ~= (Qa + Qb/256)/127
__device__ char g_Qa[DIM * DIM];
__device__ char g_Qb[DIM * DIM];
// s-state int8 limbs: s ~= (Aa + Ab/256)/127 ; int16 copy for epilogue weights
__device__ char  g_Aa[(size_t)NPAD * DIM];
__device__ char  g_Ab[(size_t)NPAD * DIM];
__device__ short g_Sw[(size_t)NPAD * DIM];

__device__ const unsigned char RT[NTILES] =
    {0,1,1,2,2,2,3,3,3,3,4,4,4,4,4,5,5,5,5,5,5,6,6,6,6,6,6,6,7,7,7,7,7,7,7,7};
__device__ const unsigned char CT[NTILES] =
    {0,0,1,0,1,2,0,1,2,3,0,1,2,3,4,0,1,2,3,4,5,0,1,2,3,4,5,6,0,1,2,3,4,5,6,7};

static __device__ __forceinline__ uint smem_u32(const void* p) {
    return (uint)__cvta_generic_to_shared(p);
}
__device__ __forceinline__ void cpasync16(uint dst, const void* src) {
    asm volatile("cp.async.cg.shared.global [%0], [%1], 16;" :: "r"(dst), "l"(src) : "memory");
}
#define CP_COMMIT asm volatile("cp.async.commit_group;" ::: "memory")
#define CP_WAIT1  asm volatile("cp.async.wait_group 1;" ::: "memory")
#define CP_WAIT0  asm volatile("cp.async.wait_group 0;" ::: "memory")

__device__ __forceinline__ void ldsm4(uint* r, uint addr) {
    asm volatile("ldmatrix.sync.aligned.m8n8.x4.shared.b16 {%0,%1,%2,%3}, [%4];"
                 : "=r"(r[0]), "=r"(r[1]), "=r"(r[2]), "=r"(r[3]) : "r"(addr));
}
__device__ __forceinline__ void mma16816(float* c, const uint* a, const uint* b) {
    asm volatile("mma.sync.aligned.m16n8k16.row.col.f32.bf16.bf16.f32 "
        "{%0,%1,%2,%3},{%4,%5,%6,%7},{%8,%9},{%0,%1,%2,%3};"
        : "+f"(c[0]), "+f"(c[1]), "+f"(c[2]), "+f"(c[3])
        : "r"(a[0]), "r"(a[1]), "r"(a[2]), "r"(a[3]), "r"(b[0]), "r"(b[1]));
}
__device__ __forceinline__ void mma16832s8(int* c, const uint* a, const uint* b) {
    asm volatile("mma.sync.aligned.m16n8k32.row.col.s32.s8.s8.s32 "
        "{%0,%1,%2,%3},{%4,%5,%6,%7},{%8,%9},{%0,%1,%2,%3};"
        : "+r"(c[0]), "+r"(c[1]), "+r"(c[2]), "+r"(c[3])
        : "r"(a[0]), "r"(a[1]), "r"(a[2]), "r"(a[3]), "r"(b[0]), "r"(b[1]));
}
__device__ __forceinline__ float clamp127(float v) {
    return fminf(fmaxf(v, -127.0f), 127.0f);
}

// ---------------------------------------------------------------------------
// Kernel 1: M = R*E; store M^T hi/lo and sign-folded M^T hi/lo, [j][d].
// ---------------------------------------------------------------------------
__global__ __launch_bounds__(256) void rot_kernel(const float* __restrict__ E,
                                                  const float* __restrict__ theta) {
    __shared__ float sm[8 * 1028];
    const int tid = threadIdx.x;
    const int j0 = blockIdx.x * 8;

    float ct[NQ], st[NQ];
#pragma unroll
    for (int i = 0; i < NQ; i++) sincosf(0.5f * theta[i], &st[i], &ct[i]);

    for (int idx = tid; idx < 8192; idx += 256) {
        int c = idx & 7, d = idx >> 3;
        sm[c * 1028 + d] = E[d * DIM + j0 + c];
    }
    __syncthreads();

    for (int i = 0; i < NQ; i++) {
        const int m = 9 - i;
        for (int t = tid; t < 4096; t += 256) {
            int c = t >> 9, p = t & 511;
            int low = p & ((1 << m) - 1);
            int d0 = ((p >> m) << (m + 1)) | low;
            int d1 = d0 | (1 << m);
            float a0 = sm[c * 1028 + d0];
            float a1 = sm[c * 1028 + d1];
            sm[c * 1028 + d0] = ct[i] * a0 - st[i] * a1;
            sm[c * 1028 + d1] = st[i] * a0 + ct[i] * a1;
        }
        __syncthreads();
    }

    for (int idx = tid; idx < 8192; idx += 256) {
        int d = idx & 1023, c = idx >> 10;
        float v = sm[c * 1028 + d];
        size_t o = (size_t)(j0 + c) * DIM + d;
        __nv_bfloat16 h = __float2bfloat16(v);
        g_Mth[o] = h;
        g_Mtl[o] = __float2bfloat16(v - __bfloat162float(h));
        float vs = (d < 512) ? v : -v;
        __nv_bfloat16 hs = __float2bfloat16(vs);
        g_Msh[o] = hs;
        g_Msl[o] = __float2bfloat16(vs - __bfloat162float(hs));
    }
}

// ---------------------------------------------------------------------------
// Kernel 2: s-state int8 limbs (radix 256, scale 127) + int16 copy (x32767).
// ---------------------------------------------------------------------------
__global__ __launch_bounds__(128) void state_kernel(const float* __restrict__ x) {
    const int tid = threadIdx.x, lane = tid & 31;
    const int n = blockIdx.x * 4 + (tid >> 5);
    float phi_u = 0.0f, plo_u = 0.0f;
    if (n < NWIN) {
        const int b = n / NWPB;
        const int pos = n - b * NWPB;
        float cs[2][5], sn[2][5];
#pragma unroll
        for (int c = 0; c < 2; c++)
#pragma unroll
            for (int k = 0; k < 5; k++) {
                float v = x[((b * 2 + c) << 12) + pos + k];
                sincosf(0.5f * v, &sn[c][k], &cs[c][k]);
            }
        phi_u = 1.0f; plo_u = 1.0f;
#pragma unroll
        for (int i = 0; i < 5; i++) {
            int bit = (lane >> (4 - i)) & 1;
            phi_u *= bit ? sn[0][i] : cs[0][i];
            plo_u *= bit ? sn[1][i] : cs[1][i];
        }
    }
    char*  Aa = g_Aa + (size_t)n * DIM;
    char*  Ab = g_Ab + (size_t)n * DIM;
    short* Sw = g_Sw + (size_t)n * DIM;
#pragma unroll 4
    for (int rep = 0; rep < 32; rep++) {
        float ph = __shfl_sync(0xffffffffu, phi_u, rep);
        float s = ph * plo_u;
        float s127 = s * 127.0f;
        float a1 = clamp127(rintf(s127));
        float a2 = clamp127(rintf((s127 - a1) * 256.0f));
        Aa[rep * 32 + lane] = (char)(int)a1;
        Ab[rep * 32 + lane] = (char)(int)a2;
        float sw = fminf(fmaxf(rintf(s * 32767.0f), -32767.0f), 32767.0f);
        Sw[rep * 32 + lane] = (short)(int)sw;
    }
}

// ---------------------------------------------------------------------------
// bf16 GEMM-stage machinery for qprep only (256 threads, 3x64KB ring).
// ---------------------------------------------------------------------------
#define QSTG 65536
#define QSMEM_BYTES (3 * QSTG + 512)

__device__ __forceinline__ void load_stage_bf16(uint sb, int buf, int tid,
                                                const __nv_bfloat16* aHp, const __nv_bfloat16* aLp,
                                                const __nv_bfloat16* bHp, const __nv_bfloat16* bLp,
                                                size_t aRow0, size_t bRow0, int kElem) {
    const int row = tid >> 1;
    const int cb = (tid & 1) * 4;
    const int r7 = row & 7;
    const uint dbase = sb + (uint)buf * QSTG + (uint)row * 128;
    const char* aH = (const char*)(aHp + aRow0 + (size_t)row * DIM + kElem);
    const char* aL = (const char*)(aLp + aRow0 + (size_t)row * DIM + kElem);
    const char* bH = (const char*)(bHp + bRow0 + (size_t)row * DIM + kElem);
    const char* bL = (const char*)(bLp + bRow0 + (size_t)row * DIM + kElem);
#pragma unroll
    for (int cc = 0; cc < 4; cc++) {
        int c = cb + cc;
        uint sw = (uint)((c ^ r7) << 4);
        cpasync16(dbase + sw,         aH + c * 16);
        cpasync16(dbase + 16384 + sw, aL + c * 16);
        cpasync16(dbase + 32768 + sw, bH + c * 16);
        cpasync16(dbase + 49152 + sw, bL + c * 16);
    }
    CP_COMMIT;
}

__device__ __forceinline__ void gemm_stage_bf16(uint sb, int buf, int arow0, int ahi,
                                                const int* nrow, int bhi, float* acc) {
    const uint abase = sb + (uint)buf * QSTG;
    const uint bbase = abase + 32768;
#pragma unroll
    for (int ks = 0; ks < 4; ks++) {
        uint ah[8], al[8], bh[16], bl[16];
#pragma unroll
        for (int i = 0; i < 2; i++) {
            int row = arow0 + 16 * i;
            uint off = (uint)row * 128 + (uint)(((ks * 2 + ahi) ^ (row & 7)) << 4);
            ldsm4(&ah[i * 4], abase + off);
            ldsm4(&al[i * 4], abase + 16384 + off);
        }
#pragma unroll
        for (int jj = 0; jj < 4; jj++) {
            uint off = (uint)nrow[jj] * 128 + (uint)(((ks * 2 + bhi) ^ (nrow[jj] & 7)) << 4);
            ldsm4(&bh[jj * 4], bbase + off);
            ldsm4(&bl[jj * 4], bbase + 16384 + off);
        }
#pragma unroll
        for (int i = 0; i < 2; i++)
#pragma unroll
            for (int j = 0; j < 8; j++) {
                float* c = &acc[(i * 8 + j) * 4];
                mma16816(c, &ah[i * 4], &bh[j * 2]);
                mma16816(c, &ah[i * 4], &bl[j * 2]);
                mma16816(c, &al[i * 4], &bh[j * 2]);
            }
    }
}

// ---------------------------------------------------------------------------
// Kernel 3: Q = M^T Sigma M -> folded int8 limbs (radix 256, scale 127).
// ---------------------------------------------------------------------------
__global__ __launch_bounds__(256, 1) void qprep_kernel() {
    extern __shared__ __align__(128) char smem[];
    const uint sb = smem_u32(smem);
    const int tid = threadIdx.x, lane = tid & 31, wid = tid >> 5;
    const int warp_m = wid & 3, warp_n = wid >> 2;
    const int r = RT[blockIdx.x], c = CT[blockIdx.x];
    const size_t aRow0 = (size_t)r * 128 * DIM;
    const size_t bRow0 = (size_t)c * 128 * DIM;

    const int arow0 = warp_m * 32 + (lane & 15);
    const int ahi = lane >> 4;
    int nrow[4];
#pragma unroll
    for (int jj = 0; jj < 4; jj++)
        nrow[jj] = warp_n * 64 + jj * 16 + ((lane >> 4) & 1) * 8 + (lane & 7);
    const int bhi = (lane >> 3) & 1;

    float acc[64];
#pragma unroll
    for (int i = 0; i < 64; i++) acc[i] = 0.0f;

    load_stage_bf16(sb, 0, tid, g_Mth, g_Mtl, g_Msh, g_Msl, aRow0, bRow0, 0);
    load_stage_bf16(sb, 1, tid, g_Mth, g_Mtl, g_Msh, g_Msl, aRow0, bRow0, 64);

    for (int s = 0; s < 16; s++) {
        if (s < 14) CP_WAIT1; else CP_WAIT0;
        __syncthreads();
        if (s + 2 < 16)
            load_stage_bf16(sb, (s + 2) % 3, tid, g_Mth, g_Mtl, g_Msh, g_Msl,
                            aRow0, bRow0, (s + 2) * 64);
        gemm_stage_bf16(sb, s % 3, arow0, ahi, nrow, bhi, acc);
        __syncthreads();
    }

    const float scale = (r == c) ? 1.0f : 2.0f;
#pragma unroll
    for (int i = 0; i < 2; i++)
#pragma unroll
        for (int j = 0; j < 8; j++) {
            float* cc = &acc[(i * 8 + j) * 4];
            int orow = r * 128 + warp_m * 32 + i * 16 + (lane >> 2);
            int ocol = c * 128 + warp_n * 64 + j * 8 + (lane & 3) * 2;
#pragma unroll
            for (int h = 0; h < 2; h++) {
                int rr = orow + h * 8;
#pragma unroll
                for (int e = 0; e < 2; e++) {
                    float q127 = cc[h * 2 + e] * scale * 127.0f;
                    float b1 = clamp127(rintf(q127));
                    float b2 = clamp127(rintf((q127 - b1) * 256.0f));
                    size_t o = (size_t)rr * DIM + ocol + e;
                    g_Qa[o] = (char)(int)b1;
                    g_Qb[o] = (char)(int)b2;
                }
            }
        }
}

// ---------------------------------------------------------------------------
// Kernel 4: exact int8 limb GEMM. 512 threads, 256-window blocks, 16 warps of
// 32x64 tiles (8 m x 2 n), 3-pass/64-acc, LDG drains, 2-stage 96KB ring.
// ---------------------------------------------------------------------------
#define STG 98304                     // A1 32K | A2 32K | B1 16K | B2 16K
#define ZSM_OFF (2 * STG)             // 196608
#define SMEM_BYTES (ZSM_OFF + 1024)   // 197632

__device__ __forceinline__ void load_stage_s8(uint sb, int s, int n0, int tid) {
    const int r = RT[s], c = CT[s];
    const uint dbase = sb + (uint)(s & 1) * STG;
    // A: 256 rows, 2 threads/row, 4 chunks per limb
    {
        const int row = tid >> 1;
        const int cb = (tid & 1) * 4;
        const int r7 = row & 7;
        const uint d = dbase + (uint)row * 128;
        const char* a1 = g_Aa + (size_t)(n0 + row) * DIM + c * 128;
        const char* a2 = g_Ab + (size_t)(n0 + row) * DIM + c * 128;
#pragma unroll
        for (int cc = 0; cc < 4; cc++) {
            int ch = cb + cc;
            uint sw = (uint)((ch ^ r7) << 4);
            cpasync16(d + sw,         a1 + ch * 16);
            cpasync16(d + 32768 + sw, a2 + ch * 16);
        }
    }
    // B: 128 rows, 4 threads/row, 2 chunks per limb
    {
        const int row = tid >> 2;
        const int cb = (tid & 3) * 2;
        const int r7 = row & 7;
        const uint d = dbase + 65536 + (uint)row * 128;
        const char* b1 = g_Qa + (size_t)(r * 128 + row) * DIM + c * 128;
        const char* b2 = g_Qb + (size_t)(r * 128 + row) * DIM + c * 128;
#pragma unroll
        for (int cc = 0; cc < 2; cc++) {
            int ch = cb + cc;
            uint sw = (uint)((ch ^ r7) << 4);
            cpasync16(d + sw,         b1 + ch * 16);
            cpasync16(d + 16384 + sw, b2 + ch * 16);
        }
    }
    CP_COMMIT;
}

// one mma pass over the stage: acc += aSel x bSel (+ optional dual combo)
__device__ __forceinline__ void s8_pass(uint A1, uint A2, uint B1, uint B2,
                                        int arow0, int ahi, const int* nrow, int bhi,
                                        int useA2, int useB2, int dual, int* acc) {
#pragma unroll
    for (int ks = 0; ks < 4; ks++) {
        uint af[8], af2[8];
#pragma unroll
        for (int i = 0; i < 2; i++) {
            int row = arow0 + 16 * i;
            uint off = (uint)row * 128 + (uint)(((ks * 2 + ahi) ^ (row & 7)) << 4);
            ldsm4(&af[i * 4], (useA2 ? A2 : A1) + off);
            if (dual) ldsm4(&af2[i * 4], A2 + off);
        }
#pragma unroll
        for (int jj = 0; jj < 4; jj++) {
            uint bf[4], bf2[4];
            uint off = (uint)nrow[jj] * 128 + (uint)(((ks * 2 + bhi) ^ (nrow[jj] & 7)) << 4);
            ldsm4(bf, (useB2 ? B2 : B1) + off);
            if (dual) ldsm4(bf2, B1 + off);
#pragma unroll
            for (int i = 0; i < 2; i++)
#pragma unroll
                for (int jh = 0; jh < 2; jh++) {
                    int idx = (i * 8 + jj * 2 + jh) * 4;
                    mma16832s8(&acc[idx], &af[i * 4], &bf[jh * 2]);
                    if (dual) mma16832s8(&acc[idx], &af2[i * 4], &bf2[jh * 2]);
                }
        }
    }
}

// drain: zp += w * acc * K ; reset acc
__device__ __forceinline__ void drain(const int* acc, float K, int n0, int colb,
                                      int warp_m, int lane, float* zp, int* accw) {
#pragma unroll
    for (int i = 0; i < 2; i++) {
        const int rg = warp_m * 32 + i * 16 + (lane >> 2);
        const short* w0p = g_Sw + (size_t)(n0 + rg) * DIM + colb;
        const short* w1p = g_Sw + (size_t)(n0 + rg + 8) * DIM + colb;
#pragma unroll
        for (int j = 0; j < 8; j++) {
            int idx = (i * 8 + j) * 4;
            short2 sw0 = __ldg((const short2*)(w0p + j * 8));
            short2 sw1 = __ldg((const short2*)(w1p + j * 8));
            zp[i * 2]     = fmaf((float)sw0.x, (float)acc[idx + 0] * K,
                            fmaf((float)sw0.y, (float)acc[idx + 1] * K, zp[i * 2]));
            zp[i * 2 + 1] = fmaf((float)sw1.x, (float)acc[idx + 2] * K,
                            fmaf((float)sw1.y, (float)acc[idx + 3] * K, zp[i * 2 + 1]));
            accw[idx + 0] = 0; accw[idx + 1] = 0; accw[idx + 2] = 0; accw[idx + 3] = 0;
        }
    }
}

__global__ __launch_bounds__(512, 1) void qmma_kernel(float* __restrict__ out) {
    extern __shared__ __align__(128) char smem[];
    const uint sb = smem_u32(smem);
    const int tid = threadIdx.x, lane = tid & 31, wid = tid >> 5;
    const int warp_m = wid >> 1, warp_n = wid & 1;    // 8 x 2
    const int n0 = blockIdx.x * 256;
    float* zsm = (float*)(smem + ZSM_OFF);
    if (tid < 256) zsm[tid] = 0.0f;

    const int arow0 = warp_m * 32 + (lane & 15);
    const int ahi = lane >> 4;
    int nrow[4];
#pragma unroll
    for (int jj = 0; jj < 4; jj++)
        nrow[jj] = warp_n * 64 + jj * 16 + ((lane >> 4) & 1) * 8 + (lane & 7);
    const int bhi = (lane >> 3) & 1;

    const float K1 = 1.0f / (16129.0f * 32767.0f);
    const float K2 = K1 / 256.0f;
    const float K3 = K1 / 65536.0f;

    int acc[64];
    float zp[4] = {0.0f, 0.0f, 0.0f, 0.0f};
#pragma unroll
    for (int i = 0; i < 64; i++) acc[i] = 0;

    load_stage_s8(sb, 0, n0, tid);

    for (int s = 0; s < NTILES; s++) {
        CP_WAIT0;                       // stage s resident
        __syncthreads();                // all warps done with buffer (s+1)&1
        if (s + 1 < NTILES) load_stage_s8(sb, s + 1, n0, tid);

        const uint A1 = sb + (uint)(s & 1) * STG;
        const uint A2 = A1 + 32768, B1 = A1 + 65536, B2 = A1 + 81920;
        const int colb = RT[s] * 128 + warp_n * 64 + (lane & 3) * 2;

        s8_pass(A1, A2, B1, B2, arow0, ahi, nrow, bhi, 0, 0, 0, acc);
        drain(acc, K1, n0, colb, warp_m, lane, zp, acc);

        s8_pass(A1, A2, B1, B2, arow0, ahi, nrow, bhi, 0, 1, 1, acc);
        drain(acc, K2, n0, colb, warp_m, lane, zp, acc);

        s8_pass(A1, A2, B1, B2, arow0, ahi, nrow, bhi, 1, 1, 0, acc);
        drain(acc, K3, n0, colb, warp_m, lane, zp, acc);
    }

    // ---- final reduction (once) ------------------------------------------
#pragma unroll
    for (int q = 0; q < 4; q++) {
        zp[q] += __shfl_xor_sync(0xffffffffu, zp[q], 1);
        zp[q] += __shfl_xor_sync(0xffffffffu, zp[q], 2);
    }
    if ((lane & 3) == 0) {
        const int rbase = warp_m * 32 + (lane >> 2);
        atomicAdd(&zsm[rbase],      zp[0]);
        atomicAdd(&zsm[rbase + 8],  zp[1]);
        atomicAdd(&zsm[rbase + 16], zp[2]);
        atomicAdd(&zsm[rbase + 24], zp[3]);
    }

    __syncthreads();
    if (tid < 256) {
        int n = n0 + tid;
        if (n < NWIN) out[n] = zsm[tid];
    }
}

// ---------------------------------------------------------------------------
extern "C" void kernel_launch(void* const* d_in, const int* in_sizes, int n_in,
                              void* d_out, int out_size) {
    const float* x     = (const float*)d_in[0];
    const float* E     = (const float*)d_in[1];
    const float* theta = (const float*)d_in[2];
    float* out = (float*)d_out;

    rot_kernel<<<DIM / 8, 256>>>(E, theta);
    state_kernel<<<NPAD / 4, 128>>>(x);

    cudaFuncSetAttribute(qprep_kernel,
                         cudaFuncAttributeMaxDynamicSharedMemorySize, QSMEM_BYTES);
    qprep_kernel<<<NTILES, 256, QSMEM_BYTES>>>();

    cudaFuncSetAttribute(qmma_kernel,
                         cudaFuncAttributeMaxDynamicSharedMemorySize, SMEM_BYTES);
    qmma_kernel<<<NPAD / 256, 512, SMEM_BYTES>>>(out);
}

// round 15
// speedup vs baseline: 1.3177x; 1.3177x over previous
#include <cuda_runtime.h>
#include <cuda_bf16.h>
#include <cstdint>

#define DIM   1024
#define NQ    10
#define NWIN  65472
#define NWPB  4092
#define NPAD  65536
#define NTILES  36

typedef unsigned long long ull;
typedef unsigned int uint;

// M^T hi/lo [j][d], and sign-folded M^T for Q = M^T Sigma M (bf16, qprep only)
__device__ __nv_bfloat16 g_Mth[DIM * DIM];
__device__ __nv_bfloat16 g_Mtl[DIM * DIM];
__device__ __nv_bfloat16 g_Msh[DIM * DIM];
__device__ __nv_bfloat16 g_Msl[DIM * DIM];
// folded Q int8 limbs (lower tiles, off-diag x2): F ~= (Qa + Qb/256)/127
__device__ char g_Qa[DIM * DIM];
__device__ char g_Qb[DIM * DIM];
// s-state int8 limbs: s ~= (Aa + Ab/256)/127 ; int16 copy for epilogue weights
__device__ char  g_Aa[(size_t)NPAD * DIM];
__device__ char  g_Ab[(size_t)NPAD * DIM];
__device__ short g_Sw[(size_t)NPAD * DIM];

__device__ const unsigned char RT[NTILES] =
    {0,1,1,2,2,2,3,3,3,3,4,4,4,4,4,5,5,5,5,5,5,6,6,6,6,6,6,6,7,7,7,7,7,7,7,7};
__device__ const unsigned char CT[NTILES] =
    {0,0,1,0,1,2,0,1,2,3,0,1,2,3,4,0,1,2,3,4,5,0,1,2,3,4,5,6,0,1,2,3,4,5,6,7};

static __device__ __forceinline__ uint smem_u32(const void* p) {
    return (uint)__cvta_generic_to_shared(p);
}
__device__ __forceinline__ void cpasync16(uint dst, const void* src) {
    asm volatile("cp.async.cg.shared.global [%0], [%1], 16;" :: "r"(dst), "l"(src) : "memory");
}
#define CP_COMMIT asm volatile("cp.async.commit_group;" ::: "memory")
#define CP_WAIT1  asm volatile("cp.async.wait_group 1;" ::: "memory")
#define CP_WAIT0  asm volatile("cp.async.wait_group 0;" ::: "memory")

__device__ __forceinline__ void ldsm4(uint* r, uint addr) {
    asm volatile("ldmatrix.sync.aligned.m8n8.x4.shared.b16 {%0,%1,%2,%3}, [%4];"
                 : "=r"(r[0]), "=r"(r[1]), "=r"(r[2]), "=r"(r[3]) : "r"(addr));
}
__device__ __forceinline__ void mma16816(float* c, const uint* a, const uint* b) {
    asm volatile("mma.sync.aligned.m16n8k16.row.col.f32.bf16.bf16.f32 "
        "{%0,%1,%2,%3},{%4,%5,%6,%7},{%8,%9},{%0,%1,%2,%3};"
        : "+f"(c[0]), "+f"(c[1]), "+f"(c[2]), "+f"(c[3])
        : "r"(a[0]), "r"(a[1]), "r"(a[2]), "r"(a[3]), "r"(b[0]), "r"(b[1]));
}
// NOTE: non-volatile on purpose — deps captured by "+r"; ptxas may schedule.
__device__ __forceinline__ void mma16832s8(int* c, const uint* a, const uint* b) {
    asm("mma.sync.aligned.m16n8k32.row.col.s32.s8.s8.s32 "
        "{%0,%1,%2,%3},{%4,%5,%6,%7},{%8,%9},{%0,%1,%2,%3};"
        : "+r"(c[0]), "+r"(c[1]), "+r"(c[2]), "+r"(c[3])
        : "r"(a[0]), "r"(a[1]), "r"(a[2]), "r"(a[3]), "r"(b[0]), "r"(b[1]));
}
__device__ __forceinline__ float clamp127(float v) {
    return fminf(fmaxf(v, -127.0f), 127.0f);
}

// ---------------------------------------------------------------------------
// Kernel 1: M = R*E; store M^T hi/lo and sign-folded M^T hi/lo, [j][d].
// ---------------------------------------------------------------------------
__global__ __launch_bounds__(256) void rot_kernel(const float* __restrict__ E,
                                                  const float* __restrict__ theta) {
    __shared__ float sm[8 * 1028];
    const int tid = threadIdx.x;
    const int j0 = blockIdx.x * 8;

    float ct[NQ], st[NQ];
#pragma unroll
    for (int i = 0; i < NQ; i++) sincosf(0.5f * theta[i], &st[i], &ct[i]);

    for (int idx = tid; idx < 8192; idx += 256) {
        int c = idx & 7, d = idx >> 3;
        sm[c * 1028 + d] = E[d * DIM + j0 + c];
    }
    __syncthreads();

    for (int i = 0; i < NQ; i++) {
        const int m = 9 - i;
        for (int t = tid; t < 4096; t += 256) {
            int c = t >> 9, p = t & 511;
            int low = p & ((1 << m) - 1);
            int d0 = ((p >> m) << (m + 1)) | low;
            int d1 = d0 | (1 << m);
            float a0 = sm[c * 1028 + d0];
            float a1 = sm[c * 1028 + d1];
            sm[c * 1028 + d0] = ct[i] * a0 - st[i] * a1;
            sm[c * 1028 + d1] = st[i] * a0 + ct[i] * a1;
        }
        __syncthreads();
    }

    for (int idx = tid; idx < 8192; idx += 256) {
        int d = idx & 1023, c = idx >> 10;
        float v = sm[c * 1028 + d];
        size_t o = (size_t)(j0 + c) * DIM + d;
        __nv_bfloat16 h = __float2bfloat16(v);
        g_Mth[o] = h;
        g_Mtl[o] = __float2bfloat16(v - __bfloat162float(h));
        float vs = (d < 512) ? v : -v;
        __nv_bfloat16 hs = __float2bfloat16(vs);
        g_Msh[o] = hs;
        g_Msl[o] = __float2bfloat16(vs - __bfloat162float(hs));
    }
}

// ---------------------------------------------------------------------------
// Kernel 2: s-state int8 limbs (radix 256, scale 127) + int16 copy (x32767).
// ---------------------------------------------------------------------------
__global__ __launch_bounds__(128) void state_kernel(const float* __restrict__ x) {
    const int tid = threadIdx.x, lane = tid & 31;
    const int n = blockIdx.x * 4 + (tid >> 5);
    float phi_u = 0.0f, plo_u = 0.0f;
    if (n < NWIN) {
        const int b = n / NWPB;
        const int pos = n - b * NWPB;
        float cs[2][5], sn[2][5];
#pragma unroll
        for (int c = 0; c < 2; c++)
#pragma unroll
            for (int k = 0; k < 5; k++) {
                float v = x[((b * 2 + c) << 12) + pos + k];
                sincosf(0.5f * v, &sn[c][k], &cs[c][k]);
            }
        phi_u = 1.0f; plo_u = 1.0f;
#pragma unroll
        for (int i = 0; i < 5; i++) {
            int bit = (lane >> (4 - i)) & 1;
            phi_u *= bit ? sn[0][i] : cs[0][i];
            plo_u *= bit ? sn[1][i] : cs[1][i];
        }
    }
    char*  Aa = g_Aa + (size_t)n * DIM;
    char*  Ab = g_Ab + (size_t)n * DIM;
    short* Sw = g_Sw + (size_t)n * DIM;
#pragma unroll 4
    for (int rep = 0; rep < 32; rep++) {
        float ph = __shfl_sync(0xffffffffu, phi_u, rep);
        float s = ph * plo_u;
        float s127 = s * 127.0f;
        float a1 = clamp127(rintf(s127));
        float a2 = clamp127(rintf((s127 - a1) * 256.0f));
        Aa[rep * 32 + lane] = (char)(int)a1;
        Ab[rep * 32 + lane] = (char)(int)a2;
        float sw = fminf(fmaxf(rintf(s * 32767.0f), -32767.0f), 32767.0f);
        Sw[rep * 32 + lane] = (short)(int)sw;
    }
}

// ---------------------------------------------------------------------------
// bf16 GEMM-stage machinery (qprep only, 256 threads).
// ---------------------------------------------------------------------------
#define STG 65536
#define W_OFF   (3 * STG)                 // 196608: int16 [128][136] w tile
#define ZSM_OFF (W_OFF + 34816)           // 231424
#define SMEM_BYTES (ZSM_OFF + 512)        // 231936 <= 232448

__device__ __forceinline__ void load_stage_bf16(uint sb, int buf, int tid,
                                                const __nv_bfloat16* aHp, const __nv_bfloat16* aLp,
                                                const __nv_bfloat16* bHp, const __nv_bfloat16* bLp,
                                                size_t aRow0, size_t bRow0, int kElem) {
    const int row = tid >> 1;
    const int cb = (tid & 1) * 4;
    const int r7 = row & 7;
    const uint dbase = sb + (uint)buf * STG + (uint)row * 128;
    const char* aH = (const char*)(aHp + aRow0 + (size_t)row * DIM + kElem);
    const char* aL = (const char*)(aLp + aRow0 + (size_t)row * DIM + kElem);
    const char* bH = (const char*)(bHp + bRow0 + (size_t)row * DIM + kElem);
    const char* bL = (const char*)(bLp + bRow0 + (size_t)row * DIM + kElem);
#pragma unroll
    for (int cc = 0; cc < 4; cc++) {
        int c = cb + cc;
        uint sw = (uint)((c ^ r7) << 4);
        cpasync16(dbase + sw,         aH + c * 16);
        cpasync16(dbase + 16384 + sw, aL + c * 16);
        cpasync16(dbase + 32768 + sw, bH + c * 16);
        cpasync16(dbase + 49152 + sw, bL + c * 16);
    }
    CP_COMMIT;
}

__device__ __forceinline__ void gemm_stage_bf16(uint sb, int buf, int arow0, int ahi,
                                                const int* nrow, int bhi, float* acc) {
    const uint abase = sb + (uint)buf * STG;
    const uint bbase = abase + 32768;
#pragma unroll
    for (int ks = 0; ks < 4; ks++) {
        uint ah[8], al[8], bh[16], bl[16];
#pragma unroll
        for (int i = 0; i < 2; i++) {
            int row = arow0 + 16 * i;
            uint off = (uint)row * 128 + (uint)(((ks * 2 + ahi) ^ (row & 7)) << 4);
            ldsm4(&ah[i * 4], abase + off);
            ldsm4(&al[i * 4], abase + 16384 + off);
        }
#pragma unroll
        for (int jj = 0; jj < 4; jj++) {
            uint off = (uint)nrow[jj] * 128 + (uint)(((ks * 2 + bhi) ^ (nrow[jj] & 7)) << 4);
            ldsm4(&bh[jj * 4], bbase + off);
            ldsm4(&bl[jj * 4], bbase + 16384 + off);
        }
#pragma unroll
        for (int i = 0; i < 2; i++)
#pragma unroll
            for (int j = 0; j < 8; j++) {
                float* c = &acc[(i * 8 + j) * 4];
                mma16816(c, &ah[i * 4], &bh[j * 2]);
                mma16816(c, &ah[i * 4], &bl[j * 2]);
                mma16816(c, &al[i * 4], &bh[j * 2]);
            }
    }
}

// ---------------------------------------------------------------------------
// Kernel 3: Q = M^T Sigma M -> folded int8 limbs (radix 256, scale 127).
// ---------------------------------------------------------------------------
__global__ __launch_bounds__(256, 1) void qprep_kernel() {
    extern __shared__ __align__(128) char smem[];
    const uint sb = smem_u32(smem);
    const int tid = threadIdx.x, lane = tid & 31, wid = tid >> 5;
    const int warp_m = wid & 3, warp_n = wid >> 2;
    const int r = RT[blockIdx.x], c = CT[blockIdx.x];
    const size_t aRow0 = (size_t)r * 128 * DIM;
    const size_t bRow0 = (size_t)c * 128 * DIM;

    const int arow0 = warp_m * 32 + (lane & 15);
    const int ahi = lane >> 4;
    int nrow[4];
#pragma unroll
    for (int jj = 0; jj < 4; jj++)
        nrow[jj] = warp_n * 64 + jj * 16 + ((lane >> 4) & 1) * 8 + (lane & 7);
    const int bhi = (lane >> 3) & 1;

    float acc[64];
#pragma unroll
    for (int i = 0; i < 64; i++) acc[i] = 0.0f;

    load_stage_bf16(sb, 0, tid, g_Mth, g_Mtl, g_Msh, g_Msl, aRow0, bRow0, 0);
    load_stage_bf16(sb, 1, tid, g_Mth, g_Mtl, g_Msh, g_Msl, aRow0, bRow0, 64);

    for (int s = 0; s < 16; s++) {
        if (s < 14) CP_WAIT1; else CP_WAIT0;
        __syncthreads();
        if (s + 2 < 16)
            load_stage_bf16(sb, (s + 2) % 3, tid, g_Mth, g_Mtl, g_Msh, g_Msl,
                            aRow0, bRow0, (s + 2) * 64);
        gemm_stage_bf16(sb, s % 3, arow0, ahi, nrow, bhi, acc);
        __syncthreads();
    }

    const float scale = (r == c) ? 1.0f : 2.0f;
#pragma unroll
    for (int i = 0; i < 2; i++)
#pragma unroll
        for (int j = 0; j < 8; j++) {
            float* cc = &acc[(i * 8 + j) * 4];
            int orow = r * 128 + warp_m * 32 + i * 16 + (lane >> 2);
            int ocol = c * 128 + warp_n * 64 + j * 8 + (lane & 3) * 2;
#pragma unroll
            for (int h = 0; h < 2; h++) {
                int rr = orow + h * 8;
#pragma unroll
                for (int e = 0; e < 2; e++) {
                    float q127 = cc[h * 2 + e] * scale * 127.0f;
                    float b1 = clamp127(rintf(q127));
                    float b2 = clamp127(rintf((q127 - b1) * 256.0f));
                    size_t o = (size_t)rr * DIM + ocol + e;
                    g_Qa[o] = (char)(int)b1;
                    g_Qb[o] = (char)(int)b2;
                }
            }
        }
}

// ---------------------------------------------------------------------------
// Kernel 4: exact int8 limb GEMM (R11 base), RAW-depth-fixed mma ordering:
// per ks load ALL frags, then 3 independent 16-wide mma sweeps.
// 256 threads, 32x64 warp tiles, 36 tile-stages, Kc=128, SMEM w-tile drains.
// ---------------------------------------------------------------------------
__device__ __forceinline__ void load_stage_s8(uint sb, int s, int n0, int tid) {
    const int r = RT[s], c = CT[s];
    const int row = tid >> 1;
    const int cb = (tid & 1) * 4;
    const int r7 = row & 7;
    const uint dbase = sb + (uint)(s % 3) * STG + (uint)row * 128;
    const char* a1 = g_Aa + (size_t)(n0 + row) * DIM + c * 128;
    const char* a2 = g_Ab + (size_t)(n0 + row) * DIM + c * 128;
    const char* b1 = g_Qa + (size_t)(r * 128 + row) * DIM + c * 128;
    const char* b2 = g_Qb + (size_t)(r * 128 + row) * DIM + c * 128;
#pragma unroll
    for (int cc = 0; cc < 4; cc++) {
        int ch = cb + cc;
        uint sw = (uint)((ch ^ r7) << 4);
        cpasync16(dbase + sw,         a1 + ch * 16);
        cpasync16(dbase + 16384 + sw, a2 + ch * 16);
        cpasync16(dbase + 32768 + sw, b1 + ch * 16);
        cpasync16(dbase + 49152 + sw, b2 + ch * 16);
    }
    CP_COMMIT;
}

// w tile: int16 [128 rows][pitch 136] ; row stride 272 B (16B-aligned).
__device__ __forceinline__ void load_w(uint sb, int s, int n0, int tid) {
    const int rt = RT[s];
    const int row = tid >> 1;
    const int half = tid & 1;
    const uint dst = sb + W_OFF + (uint)row * 272 + (uint)half * 128;
    const char* src = (const char*)(g_Sw + (size_t)(n0 + row) * DIM + rt * 128 + half * 64);
#pragma unroll
    for (int q = 0; q < 8; q++)
        cpasync16(dst + q * 16, src + q * 16);
    CP_COMMIT;
}

__global__ __launch_bounds__(256, 1) void qmma_kernel(float* __restrict__ out) {
    extern __shared__ __align__(128) char smem[];
    const uint sb = smem_u32(smem);
    const int tid = threadIdx.x, lane = tid & 31, wid = tid >> 5;
    const int warp_m = wid & 3, warp_n = wid >> 2;
    const int n0 = blockIdx.x * 128;
    float* zsm = (float*)(smem + ZSM_OFF);
    if (tid < 128) zsm[tid] = 0.0f;

    const int arow0 = warp_m * 32 + (lane & 15);
    const int ahi = lane >> 4;
    int nrow[4];
#pragma unroll
    for (int jj = 0; jj < 4; jj++)
        nrow[jj] = warp_n * 64 + jj * 16 + ((lane >> 4) & 1) * 8 + (lane & 7);
    const int bhi = (lane >> 3) & 1;

    const float K1 = 1.0f / (16129.0f * 32767.0f);
    const float K2 = K1 / 256.0f;
    const float K3 = K1 / 65536.0f;

    int i11[64], imd[64];
    float zp[4] = {0.0f, 0.0f, 0.0f, 0.0f};
#pragma unroll
    for (int i = 0; i < 64; i++) { i11[i] = 0; imd[i] = 0; }

    load_stage_s8(sb, 0, n0, tid);
    load_stage_s8(sb, 1, n0, tid);

    // per-thread w smem base (conflict-free: bank = 4*(lane>>2)+(lane&3))
    const char* wbase = smem + W_OFF + (uint)(warp_n * 64 + (lane & 3) * 2) * 2;

    for (int s = 0; s < NTILES; s++) {
        CP_WAIT1;                       // tile s resident (leaves tile s+1 in flight)
        __syncthreads();                // all drains of s-1 done -> w reusable
        load_w(sb, s, n0, tid);         // group W_s
        if (s + 2 < NTILES) load_stage_s8(sb, s + 2, n0, tid);  // group T_{s+2}

        const uint A1 = sb + (uint)(s % 3) * STG;
        const uint A2 = A1 + 16384, B1 = A1 + 32768, B2 = A1 + 49152;

        // ---- pass 1&2 (fused accs, sweep-ordered to break mma RAW chains) -
#pragma unroll
        for (int ks = 0; ks < 4; ks++) {
            uint a1f[8], a2f[8], b1f[16], b2f[16];
#pragma unroll
            for (int i = 0; i < 2; i++) {
                int row = arow0 + 16 * i;
                uint off = (uint)row * 128 + (uint)(((ks * 2 + ahi) ^ (row & 7)) << 4);
                ldsm4(&a1f[i * 4], A1 + off);
                ldsm4(&a2f[i * 4], A2 + off);
            }
#pragma unroll
            for (int jj = 0; jj < 4; jj++) {
                uint off = (uint)nrow[jj] * 128 + (uint)(((ks * 2 + bhi) ^ (nrow[jj] & 7)) << 4);
                ldsm4(&b1f[jj * 4], B1 + off);
                ldsm4(&b2f[jj * 4], B2 + off);
            }
            // sweep 1: i11 += a1 x b1   (16 independent mma)
#pragma unroll
            for (int i = 0; i < 2; i++)
#pragma unroll
                for (int jj = 0; jj < 4; jj++)
#pragma unroll
                    for (int jh = 0; jh < 2; jh++)
                        mma16832s8(&i11[(i * 8 + jj * 2 + jh) * 4], &a1f[i * 4], &b1f[jj * 4 + jh * 2]);
            // sweep 2: imd += a1 x b2   (16 independent mma)
#pragma unroll
            for (int i = 0; i < 2; i++)
#pragma unroll
                for (int jj = 0; jj < 4; jj++)
#pragma unroll
                    for (int jh = 0; jh < 2; jh++)
                        mma16832s8(&imd[(i * 8 + jj * 2 + jh) * 4], &a1f[i * 4], &b2f[jj * 4 + jh * 2]);
            // sweep 3: imd += a2 x b1   (RAW distance 16 from sweep 2)
#pragma unroll
            for (int i = 0; i < 2; i++)
#pragma unroll
                for (int jj = 0; jj < 4; jj++)
#pragma unroll
                    for (int jh = 0; jh < 2; jh++)
                        mma16832s8(&imd[(i * 8 + jj * 2 + jh) * 4], &a2f[i * 4], &b1f[jj * 4 + jh * 2]);
        }

        // w tile resident? (W_s older than T_{s+2}; leave only T_{s+2} in flight)
        if (s + 2 < NTILES) CP_WAIT1; else CP_WAIT0;

        // ---- drain A: zp += w*(i11*K1 + imd*K2) ; reset -------------------
#pragma unroll
        for (int i = 0; i < 2; i++) {
            const int rg = warp_m * 32 + i * 16 + (lane >> 2);
            const char* w0r = wbase + (uint)rg * 272;
            const char* w1r = wbase + (uint)(rg + 8) * 272;
#pragma unroll
            for (int j = 0; j < 8; j++) {
                int idx = (i * 8 + j) * 4;
                short2 sw0 = *(const short2*)(w0r + j * 16);
                short2 sw1 = *(const short2*)(w1r + j * 16);
                float t0 = fmaf((float)imd[idx + 0], K2, (float)i11[idx + 0] * K1);
                float t1 = fmaf((float)imd[idx + 1], K2, (float)i11[idx + 1] * K1);
                float t2 = fmaf((float)imd[idx + 2], K2, (float)i11[idx + 2] * K1);
                float t3 = fmaf((float)imd[idx + 3], K2, (float)i11[idx + 3] * K1);
                zp[i * 2]     = fmaf((float)sw0.x, t0, fmaf((float)sw0.y, t1, zp[i * 2]));
                zp[i * 2 + 1] = fmaf((float)sw1.x, t2, fmaf((float)sw1.y, t3, zp[i * 2 + 1]));
                i11[idx + 0] = 0; i11[idx + 1] = 0; i11[idx + 2] = 0; i11[idx + 3] = 0;
                imd[idx + 0] = 0; imd[idx + 1] = 0; imd[idx + 2] = 0; imd[idx + 3] = 0;
            }
        }

        // ---- pass 3: a2 x b2 -> i11 (reused; reuse distance 16) ----------
#pragma unroll
        for (int ks = 0; ks < 4; ks++) {
            uint a2f[8], b2f[16];
#pragma unroll
            for (int i = 0; i < 2; i++) {
                int row = arow0 + 16 * i;
                uint off = (uint)row * 128 + (uint)(((ks * 2 + ahi) ^ (row & 7)) << 4);
                ldsm4(&a2f[i * 4], A2 + off);
            }
#pragma unroll
            for (int jj = 0; jj < 4; jj++) {
                uint off = (uint)nrow[jj] * 128 + (uint)(((ks * 2 + bhi) ^ (nrow[jj] & 7)) << 4);
                ldsm4(&b2f[jj * 4], B2 + off);
            }
#pragma unroll
            for (int i = 0; i < 2; i++)
#pragma unroll
                for (int jj = 0; jj < 4; jj++)
#pragma unroll
                    for (int jh = 0; jh < 2; jh++)
                        mma16832s8(&i11[(i * 8 + jj * 2 + jh) * 4], &a2f[i * 4], &b2f[jj * 4 + jh * 2]);
        }

        // ---- drain B: zp += w*(i11*K3) ; reset ----------------------------
#pragma unroll
        for (int i = 0; i < 2; i++) {
            const int rg = warp_m * 32 + i * 16 + (lane >> 2);
            const char* w0r = wbase + (uint)rg * 272;
            const char* w1r = wbase + (uint)(rg + 8) * 272;
#pragma unroll
            for (int j = 0; j < 8; j++) {
                int idx = (i * 8 + j) * 4;
                short2 sw0 = *(const short2*)(w0r + j * 16);
                short2 sw1 = *(const short2*)(w1r + j * 16);
                zp[i * 2]     = fmaf((float)sw0.x, (float)i11[idx + 0] * K3,
                                fmaf((float)sw0.y, (float)i11[idx + 1] * K3, zp[i * 2]));
                zp[i * 2 + 1] = fmaf((float)sw1.x, (float)i11[idx + 2] * K3,
                                fmaf((float)sw1.y, (float)i11[idx + 3] * K3, zp[i * 2 + 1]));
                i11[idx + 0] = 0; i11[idx + 1] = 0; i11[idx + 2] = 0; i11[idx + 3] = 0;
            }
        }
    }

    // ---- final reduction (once) ------------------------------------------
#pragma unroll
    for (int q = 0; q < 4; q++) {
        zp[q] += __shfl_xor_sync(0xffffffffu, zp[q], 1);
        zp[q] += __shfl_xor_sync(0xffffffffu, zp[q], 2);
    }
    if ((lane & 3) == 0) {
        const int rbase = warp_m * 32 + (lane >> 2);
        atomicAdd(&zsm[rbase],      zp[0]);
        atomicAdd(&zsm[rbase + 8],  zp[1]);
        atomicAdd(&zsm[rbase + 16], zp[2]);
        atomicAdd(&zsm[rbase + 24], zp[3]);
    }

    __syncthreads();
    if (tid < 128) {
        int n = n0 + tid;
        if (n < NWIN) out[n] = zsm[tid];
    }
}

// ---------------------------------------------------------------------------
extern "C" void kernel_launch(void* const* d_in, const int* in_sizes, int n_in,
                              void* d_out, int out_size) {
    const float* x     = (const float*)d_in[0];
    const float* E     = (const float*)d_in[1];
    const float* theta = (const float*)d_in[2];
    float* out = (float*)d_out;

    rot_kernel<<<DIM / 8, 256>>>(E, theta);
    state_kernel<<<NPAD / 4, 128>>>(x);

    cudaFuncSetAttribute(qprep_kernel,
                         cudaFuncAttributeMaxDynamicSharedMemorySize, SMEM_BYTES);
    qprep_kernel<<<NTILES, 256, SMEM_BYTES>>>();

    cudaFuncSetAttribute(qmma_kernel,
                         cudaFuncAttributeMaxDynamicSharedMemorySize, SMEM_BYTES);
    qmma_kernel<<<NPAD / 128, 256, SMEM_BYTES>>>(out);
}

// round 16
// speedup vs baseline: 1.6361x; 1.2416x over previous
#include <cuda_runtime.h>
#include <cuda_bf16.h>
#include <cstdint>

#define DIM   1024
#define NQ    10
#define NWIN  65472
#define NWPB  4092
#define NPAD  65536
#define NTILES  36

typedef unsigned long long ull;
typedef unsigned int uint;

// M^T hi/lo [j][d], and sign-folded M^T for Q = M^T Sigma M (bf16, qprep only)
__device__ __nv_bfloat16 g_Mth[DIM * DIM];
__device__ __nv_bfloat16 g_Mtl[DIM * DIM];
__device__ __nv_bfloat16 g_Msh[DIM * DIM];
__device__ __nv_bfloat16 g_Msl[DIM * DIM];
// folded Q int8 limbs (lower tiles, off-diag x2): F ~= (Qa + Qb/256)/127
__device__ char g_Qa[DIM * DIM];
__device__ char g_Qb[DIM * DIM];
// s-state int8 limbs: s ~= (Aa + Ab/256)/127 ; int16 copy for epilogue weights
__device__ char  g_Aa[(size_t)NPAD * DIM];
__device__ char  g_Ab[(size_t)NPAD * DIM];
__device__ short g_Sw[(size_t)NPAD * DIM];

// r-major, c inner: row r's last tile is the diagonal (c == r)
__device__ const unsigned char RT[NTILES] =
    {0,1,1,2,2,2,3,3,3,3,4,4,4,4,4,5,5,5,5,5,5,6,6,6,6,6,6,6,7,7,7,7,7,7,7,7};
__device__ const unsigned char CT[NTILES] =
    {0,0,1,0,1,2,0,1,2,3,0,1,2,3,4,0,1,2,3,4,5,0,1,2,3,4,5,6,0,1,2,3,4,5,6,7};

static __device__ __forceinline__ uint smem_u32(const void* p) {
    return (uint)__cvta_generic_to_shared(p);
}
__device__ __forceinline__ void cpasync16(uint dst, const void* src) {
    asm volatile("cp.async.cg.shared.global [%0], [%1], 16;" :: "r"(dst), "l"(src) : "memory");
}
#define CP_COMMIT asm volatile("cp.async.commit_group;" ::: "memory")
#define CP_WAIT1  asm volatile("cp.async.wait_group 1;" ::: "memory")
#define CP_WAIT0  asm volatile("cp.async.wait_group 0;" ::: "memory")

__device__ __forceinline__ void ldsm4(uint* r, uint addr) {
    asm volatile("ldmatrix.sync.aligned.m8n8.x4.shared.b16 {%0,%1,%2,%3}, [%4];"
                 : "=r"(r[0]), "=r"(r[1]), "=r"(r[2]), "=r"(r[3]) : "r"(addr));
}
__device__ __forceinline__ void mma16816(float* c, const uint* a, const uint* b) {
    asm volatile("mma.sync.aligned.m16n8k16.row.col.f32.bf16.bf16.f32 "
        "{%0,%1,%2,%3},{%4,%5,%6,%7},{%8,%9},{%0,%1,%2,%3};"
        : "+f"(c[0]), "+f"(c[1]), "+f"(c[2]), "+f"(c[3])
        : "r"(a[0]), "r"(a[1]), "r"(a[2]), "r"(a[3]), "r"(b[0]), "r"(b[1]));
}
__device__ __forceinline__ void mma16832s8(int* c, const uint* a, const uint* b) {
    asm("mma.sync.aligned.m16n8k32.row.col.s32.s8.s8.s32 "
        "{%0,%1,%2,%3},{%4,%5,%6,%7},{%8,%9},{%0,%1,%2,%3};"
        : "+r"(c[0]), "+r"(c[1]), "+r"(c[2]), "+r"(c[3])
        : "r"(a[0]), "r"(a[1]), "r"(a[2]), "r"(a[3]), "r"(b[0]), "r"(b[1]));
}
__device__ __forceinline__ float clamp127(float v) {
    return fminf(fmaxf(v, -127.0f), 127.0f);
}

// ---------------------------------------------------------------------------
// Kernel 1: M = R*E; store M^T hi/lo and sign-folded M^T hi/lo, [j][d].
// ---------------------------------------------------------------------------
__global__ __launch_bounds__(256) void rot_kernel(const float* __restrict__ E,
                                                  const float* __restrict__ theta) {
    __shared__ float sm[8 * 1028];
    const int tid = threadIdx.x;
    const int j0 = blockIdx.x * 8;

    float ct[NQ], st[NQ];
#pragma unroll
    for (int i = 0; i < NQ; i++) sincosf(0.5f * theta[i], &st[i], &ct[i]);

    for (int idx = tid; idx < 8192; idx += 256) {
        int c = idx & 7, d = idx >> 3;
        sm[c * 1028 + d] = E[d * DIM + j0 + c];
    }
    __syncthreads();

    for (int i = 0; i < NQ; i++) {
        const int m = 9 - i;
        for (int t = tid; t < 4096; t += 256) {
            int c = t >> 9, p = t & 511;
            int low = p & ((1 << m) - 1);
            int d0 = ((p >> m) << (m + 1)) | low;
            int d1 = d0 | (1 << m);
            float a0 = sm[c * 1028 + d0];
            float a1 = sm[c * 1028 + d1];
            sm[c * 1028 + d0] = ct[i] * a0 - st[i] * a1;
            sm[c * 1028 + d1] = st[i] * a0 + ct[i] * a1;
        }
        __syncthreads();
    }

    for (int idx = tid; idx < 8192; idx += 256) {
        int d = idx & 1023, c = idx >> 10;
        float v = sm[c * 1028 + d];
        size_t o = (size_t)(j0 + c) * DIM + d;
        __nv_bfloat16 h = __float2bfloat16(v);
        g_Mth[o] = h;
        g_Mtl[o] = __float2bfloat16(v - __bfloat162float(h));
        float vs = (d < 512) ? v : -v;
        __nv_bfloat16 hs = __float2bfloat16(vs);
        g_Msh[o] = hs;
        g_Msl[o] = __float2bfloat16(vs - __bfloat162float(hs));
    }
}

// ---------------------------------------------------------------------------
// Kernel 2: s-state int8 limbs (radix 256, scale 127) + int16 copy (x32767).
// ---------------------------------------------------------------------------
__global__ __launch_bounds__(128) void state_kernel(const float* __restrict__ x) {
    const int tid = threadIdx.x, lane = tid & 31;
    const int n = blockIdx.x * 4 + (tid >> 5);
    float phi_u = 0.0f, plo_u = 0.0f;
    if (n < NWIN) {
        const int b = n / NWPB;
        const int pos = n - b * NWPB;
        float cs[2][5], sn[2][5];
#pragma unroll
        for (int c = 0; c < 2; c++)
#pragma unroll
            for (int k = 0; k < 5; k++) {
                float v = x[((b * 2 + c) << 12) + pos + k];
                sincosf(0.5f * v, &sn[c][k], &cs[c][k]);
            }
        phi_u = 1.0f; plo_u = 1.0f;
#pragma unroll
        for (int i = 0; i < 5; i++) {
            int bit = (lane >> (4 - i)) & 1;
            phi_u *= bit ? sn[0][i] : cs[0][i];
            plo_u *= bit ? sn[1][i] : cs[1][i];
        }
    }
    char*  Aa = g_Aa + (size_t)n * DIM;
    char*  Ab = g_Ab + (size_t)n * DIM;
    short* Sw = g_Sw + (size_t)n * DIM;
#pragma unroll 4
    for (int rep = 0; rep < 32; rep++) {
        float ph = __shfl_sync(0xffffffffu, phi_u, rep);
        float s = ph * plo_u;
        float s127 = s * 127.0f;
        float a1 = clamp127(rintf(s127));
        float a2 = clamp127(rintf((s127 - a1) * 256.0f));
        Aa[rep * 32 + lane] = (char)(int)a1;
        Ab[rep * 32 + lane] = (char)(int)a2;
        float sw = fminf(fmaxf(rintf(s * 32767.0f), -32767.0f), 32767.0f);
        Sw[rep * 32 + lane] = (short)(int)sw;
    }
}

// ---------------------------------------------------------------------------
// bf16 GEMM-stage machinery (qprep only, 256 threads).
// ---------------------------------------------------------------------------
#define STG 65536
#define ZSM_OFF (3 * STG)
#define SMEM_BYTES (3 * STG + 512)

__device__ __forceinline__ void load_stage_bf16(uint sb, int buf, int tid,
                                                const __nv_bfloat16* aHp, const __nv_bfloat16* aLp,
                                                const __nv_bfloat16* bHp, const __nv_bfloat16* bLp,
                                                size_t aRow0, size_t bRow0, int kElem) {
    const int row = tid >> 1;
    const int cb = (tid & 1) * 4;
    const int r7 = row & 7;
    const uint dbase = sb + (uint)buf * STG + (uint)row * 128;
    const char* aH = (const char*)(aHp + aRow0 + (size_t)row * DIM + kElem);
    const char* aL = (const char*)(aLp + aRow0 + (size_t)row * DIM + kElem);
    const char* bH = (const char*)(bHp + bRow0 + (size_t)row * DIM + kElem);
    const char* bL = (const char*)(bLp + bRow0 + (size_t)row * DIM + kElem);
#pragma unroll
    for (int cc = 0; cc < 4; cc++) {
        int c = cb + cc;
        uint sw = (uint)((c ^ r7) << 4);
        cpasync16(dbase + sw,         aH + c * 16);
        cpasync16(dbase + 16384 + sw, aL + c * 16);
        cpasync16(dbase + 32768 + sw, bH + c * 16);
        cpasync16(dbase + 49152 + sw, bL + c * 16);
    }
    CP_COMMIT;
}

__device__ __forceinline__ void gemm_stage_bf16(uint sb, int buf, int arow0, int ahi,
                                                const int* nrow, int bhi, float* acc) {
    const uint abase = sb + (uint)buf * STG;
    const uint bbase = abase + 32768;
#pragma unroll
    for (int ks = 0; ks < 4; ks++) {
        uint ah[8], al[8], bh[16], bl[16];
#pragma unroll
        for (int i = 0; i < 2; i++) {
            int row = arow0 + 16 * i;
            uint off = (uint)row * 128 + (uint)(((ks * 2 + ahi) ^ (row & 7)) << 4);
            ldsm4(&ah[i * 4], abase + off);
            ldsm4(&al[i * 4], abase + 16384 + off);
        }
#pragma unroll
        for (int jj = 0; jj < 4; jj++) {
            uint off = (uint)nrow[jj] * 128 + (uint)(((ks * 2 + bhi) ^ (nrow[jj] & 7)) << 4);
            ldsm4(&bh[jj * 4], bbase + off);
            ldsm4(&bl[jj * 4], bbase + 16384 + off);
        }
#pragma unroll
        for (int i = 0; i < 2; i++)
#pragma unroll
            for (int j = 0; j < 8; j++) {
                float* c = &acc[(i * 8 + j) * 4];
                mma16816(c, &ah[i * 4], &bh[j * 2]);
                mma16816(c, &ah[i * 4], &bl[j * 2]);
                mma16816(c, &al[i * 4], &bh[j * 2]);
            }
    }
}

// ---------------------------------------------------------------------------
// Kernel 3: Q = M^T Sigma M -> folded int8 limbs (radix 256, scale 127).
// ---------------------------------------------------------------------------
__global__ __launch_bounds__(256, 1) void qprep_kernel() {
    extern __shared__ __align__(128) char smem[];
    const uint sb = smem_u32(smem);
    const int tid = threadIdx.x, lane = tid & 31, wid = tid >> 5;
    const int warp_m = wid & 3, warp_n = wid >> 2;
    const int r = RT[blockIdx.x], c = CT[blockIdx.x];
    const size_t aRow0 = (size_t)r * 128 * DIM;
    const size_t bRow0 = (size_t)c * 128 * DIM;

    const int arow0 = warp_m * 32 + (lane & 15);
    const int ahi = lane >> 4;
    int nrow[4];
#pragma unroll
    for (int jj = 0; jj < 4; jj++)
        nrow[jj] = warp_n * 64 + jj * 16 + ((lane >> 4) & 1) * 8 + (lane & 7);
    const int bhi = (lane >> 3) & 1;

    float acc[64];
#pragma unroll
    for (int i = 0; i < 64; i++) acc[i] = 0.0f;

    load_stage_bf16(sb, 0, tid, g_Mth, g_Mtl, g_Msh, g_Msl, aRow0, bRow0, 0);
    load_stage_bf16(sb, 1, tid, g_Mth, g_Mtl, g_Msh, g_Msl, aRow0, bRow0, 64);

    for (int s = 0; s < 16; s++) {
        if (s < 14) CP_WAIT1; else CP_WAIT0;
        __syncthreads();
        if (s + 2 < 16)
            load_stage_bf16(sb, (s + 2) % 3, tid, g_Mth, g_Mtl, g_Msh, g_Msl,
                            aRow0, bRow0, (s + 2) * 64);
        gemm_stage_bf16(sb, s % 3, arow0, ahi, nrow, bhi, acc);
        __syncthreads();
    }

    const float scale = (r == c) ? 1.0f : 2.0f;
#pragma unroll
    for (int i = 0; i < 2; i++)
#pragma unroll
        for (int j = 0; j < 8; j++) {
            float* cc = &acc[(i * 8 + j) * 4];
            int orow = r * 128 + warp_m * 32 + i * 16 + (lane >> 2);
            int ocol = c * 128 + warp_n * 64 + j * 8 + (lane & 3) * 2;
#pragma unroll
            for (int h = 0; h < 2; h++) {
                int rr = orow + h * 8;
#pragma unroll
                for (int e = 0; e < 2; e++) {
                    float q127 = cc[h * 2 + e] * scale * 127.0f;
                    float b1 = clamp127(rintf(q127));
                    float b2 = clamp127(rintf((q127 - b1) * 256.0f));
                    size_t o = (size_t)rr * DIM + ocol + e;
                    g_Qa[o] = (char)(int)b1;
                    g_Qb[o] = (char)(int)b2;
                }
            }
        }
}

// ---------------------------------------------------------------------------
// Kernel 4: exact int8 limb GEMM with ROW-ACCUMULATED drains.
// 3 integer banks (i11/imd/i22) accumulate across all c-tiles of a row r;
// one drain per row (8 total). 256 threads, 32x64 warp tiles, Kc=128, 3-ring.
// ---------------------------------------------------------------------------
__device__ __forceinline__ void load_stage_s8(uint sb, int s, int n0, int tid) {
    const int r = RT[s], c = CT[s];
    const int row = tid >> 1;
    const int cb = (tid & 1) * 4;
    const int r7 = row & 7;
    const uint dbase = sb + (uint)(s % 3) * STG + (uint)row * 128;
    const char* a1 = g_Aa + (size_t)(n0 + row) * DIM + c * 128;
    const char* a2 = g_Ab + (size_t)(n0 + row) * DIM + c * 128;
    const char* b1 = g_Qa + (size_t)(r * 128 + row) * DIM + c * 128;
    const char* b2 = g_Qb + (size_t)(r * 128 + row) * DIM + c * 128;
#pragma unroll
    for (int cc = 0; cc < 4; cc++) {
        int ch = cb + cc;
        uint sw = (uint)((ch ^ r7) << 4);
        cpasync16(dbase + sw,         a1 + ch * 16);
        cpasync16(dbase + 16384 + sw, a2 + ch * 16);
        cpasync16(dbase + 32768 + sw, b1 + ch * 16);
        cpasync16(dbase + 49152 + sw, b2 + ch * 16);
    }
    CP_COMMIT;
}

__global__ __launch_bounds__(256, 1) void qmma_kernel(float* __restrict__ out) {
    extern __shared__ __align__(128) char smem[];
    const uint sb = smem_u32(smem);
    const int tid = threadIdx.x, lane = tid & 31, wid = tid >> 5;
    const int warp_m = wid & 3, warp_n = wid >> 2;
    const int n0 = blockIdx.x * 128;
    float* zsm = (float*)(smem + ZSM_OFF);
    if (tid < 128) zsm[tid] = 0.0f;

    const int arow0 = warp_m * 32 + (lane & 15);
    const int ahi = lane >> 4;
    int nrow[4];
#pragma unroll
    for (int jj = 0; jj < 4; jj++)
        nrow[jj] = warp_n * 64 + jj * 16 + ((lane >> 4) & 1) * 8 + (lane & 7);
    const int bhi = (lane >> 3) & 1;

    const float K1 = 1.0f / (16129.0f * 32767.0f);
    const float K2 = K1 / 256.0f;
    const float K3 = K1 / 65536.0f;

    int i11[64], imd[64], i22[64];
    float zp[4] = {0.0f, 0.0f, 0.0f, 0.0f};
#pragma unroll
    for (int i = 0; i < 64; i++) { i11[i] = 0; imd[i] = 0; i22[i] = 0; }

    load_stage_s8(sb, 0, n0, tid);
    load_stage_s8(sb, 1, n0, tid);

    for (int s = 0; s < NTILES; s++) {
        if (s < NTILES - 2) CP_WAIT1; else CP_WAIT0;
        __syncthreads();
        if (s + 2 < NTILES) load_stage_s8(sb, s + 2, n0, tid);

        const uint A1 = sb + (uint)(s % 3) * STG;
        const uint A2 = A1 + 16384, B1 = A1 + 32768, B2 = A1 + 49152;

        // ---- single combined pass: 4 limb sweeps, frags loaded once -------
#pragma unroll
        for (int ks = 0; ks < 4; ks++) {
            uint a1f[8], a2f[8], b1f[16], b2f[16];
#pragma unroll
            for (int i = 0; i < 2; i++) {
                int row = arow0 + 16 * i;
                uint off = (uint)row * 128 + (uint)(((ks * 2 + ahi) ^ (row & 7)) << 4);
                ldsm4(&a1f[i * 4], A1 + off);
                ldsm4(&a2f[i * 4], A2 + off);
            }
#pragma unroll
            for (int jj = 0; jj < 4; jj++) {
                uint off = (uint)nrow[jj] * 128 + (uint)(((ks * 2 + bhi) ^ (nrow[jj] & 7)) << 4);
                ldsm4(&b1f[jj * 4], B1 + off);
                ldsm4(&b2f[jj * 4], B2 + off);
            }
#pragma unroll
            for (int i = 0; i < 2; i++)
#pragma unroll
                for (int jj = 0; jj < 4; jj++)
#pragma unroll
                    for (int jh = 0; jh < 2; jh++) {
                        int idx = (i * 8 + jj * 2 + jh) * 4;
                        mma16832s8(&i11[idx], &a1f[i * 4], &b1f[jj * 4 + jh * 2]);
                        mma16832s8(&imd[idx], &a1f[i * 4], &b2f[jj * 4 + jh * 2]);
                        mma16832s8(&imd[idx], &a2f[i * 4], &b1f[jj * 4 + jh * 2]);
                        mma16832s8(&i22[idx], &a2f[i * 4], &b2f[jj * 4 + jh * 2]);
                    }
        }

        // ---- drain once per row (diagonal tile: c == r) -------------------
        if (RT[s] == CT[s]) {
            const int colb = RT[s] * 128 + warp_n * 64 + (lane & 3) * 2;
#pragma unroll
            for (int i = 0; i < 2; i++) {
                const int rg = warp_m * 32 + i * 16 + (lane >> 2);
                const short* w0p = g_Sw + (size_t)(n0 + rg) * DIM + colb;
                const short* w1p = g_Sw + (size_t)(n0 + rg + 8) * DIM + colb;
#pragma unroll
                for (int j = 0; j < 8; j++) {
                    int idx = (i * 8 + j) * 4;
                    short2 sw0 = __ldg((const short2*)(w0p + j * 8));
                    short2 sw1 = __ldg((const short2*)(w1p + j * 8));
                    float t0 = fmaf((float)i22[idx + 0], K3,
                               fmaf((float)imd[idx + 0], K2, (float)i11[idx + 0] * K1));
                    float t1 = fmaf((float)i22[idx + 1], K3,
                               fmaf((float)imd[idx + 1], K2, (float)i11[idx + 1] * K1));
                    float t2 = fmaf((float)i22[idx + 2], K3,
                               fmaf((float)imd[idx + 2], K2, (float)i11[idx + 2] * K1));
                    float t3 = fmaf((float)i22[idx + 3], K3,
                               fmaf((float)imd[idx + 3], K2, (float)i11[idx + 3] * K1));
                    zp[i * 2]     = fmaf((float)sw0.x, t0, fmaf((float)sw0.y, t1, zp[i * 2]));
                    zp[i * 2 + 1] = fmaf((float)sw1.x, t2, fmaf((float)sw1.y, t3, zp[i * 2 + 1]));
                    i11[idx + 0] = 0; i11[idx + 1] = 0; i11[idx + 2] = 0; i11[idx + 3] = 0;
                    imd[idx + 0] = 0; imd[idx + 1] = 0; imd[idx + 2] = 0; imd[idx + 3] = 0;
                    i22[idx + 0] = 0; i22[idx + 1] = 0; i22[idx + 2] = 0; i22[idx + 3] = 0;
                }
            }
        }
    }

    // ---- final reduction (once) ------------------------------------------
#pragma unroll
    for (int q = 0; q < 4; q++) {
        zp[q] += __shfl_xor_sync(0xffffffffu, zp[q], 1);
        zp[q] += __shfl_xor_sync(0xffffffffu, zp[q], 2);
    }
    if ((lane & 3) == 0) {
        const int rbase = warp_m * 32 + (lane >> 2);
        atomicAdd(&zsm[rbase],      zp[0]);
        atomicAdd(&zsm[rbase + 8],  zp[1]);
        atomicAdd(&zsm[rbase + 16], zp[2]);
        atomicAdd(&zsm[rbase + 24], zp[3]);
    }

    __syncthreads();
    if (tid < 128) {
        int n = n0 + tid;
        if (n < NWIN) out[n] = zsm[tid];
    }
}

// ---------------------------------------------------------------------------
extern "C" void kernel_launch(void* const* d_in, const int* in_sizes, int n_in,
                              void* d_out, int out_size) {
    const float* x     = (const float*)d_in[0];
    const float* E     = (const float*)d_in[1];
    const float* theta = (const float*)d_in[2];
    float* out = (float*)d_out;

    rot_kernel<<<DIM / 8, 256>>>(E, theta);
    state_kernel<<<NPAD / 4, 128>>>(x);

    cudaFuncSetAttribute(qprep_kernel,
                         cudaFuncAttributeMaxDynamicSharedMemorySize, SMEM_BYTES);
    qprep_kernel<<<NTILES, 256, SMEM_BYTES>>>();

    cudaFuncSetAttribute(qmma_kernel,
                         cudaFuncAttributeMaxDynamicSharedMemorySize, SMEM_BYTES);
    qmma_kernel<<<NPAD / 128, 256, SMEM_BYTES>>>(out);
}

// round 17
// speedup vs baseline: 1.6539x; 1.0109x over previous
#include <cuda_runtime.h>
#include <cuda_bf16.h>
#include <cstdint>

#define DIM   1024
#define NQ    10
#define NWIN  65472
#define NWPB  4092
#define NPAD  65536
#define NTILES  36

typedef unsigned long long ull;
typedef unsigned int uint;

// M^T hi/lo [j][d], and sign-folded M^T for Q = M^T Sigma M (bf16, qprep only)
__device__ __nv_bfloat16 g_Mth[DIM * DIM];
__device__ __nv_bfloat16 g_Mtl[DIM * DIM];
__device__ __nv_bfloat16 g_Msh[DIM * DIM];
__device__ __nv_bfloat16 g_Msl[DIM * DIM];
// folded Q int8 limbs (lower tiles, off-diag x2): F ~= (Qa + Qb/256)/127
__device__ char g_Qa[DIM * DIM];
__device__ char g_Qb[DIM * DIM];
// s-state int8 limbs: s ~= (Aa + Ab/256)/127 ; int16 copy for epilogue weights
__device__ char  g_Aa[(size_t)NPAD * DIM];
__device__ char  g_Ab[(size_t)NPAD * DIM];
__device__ short g_Sw[(size_t)NPAD * DIM];

// r-major, c inner: row r's last tile is the diagonal (c == r)
__device__ const unsigned char RT[NTILES] =
    {0,1,1,2,2,2,3,3,3,3,4,4,4,4,4,5,5,5,5,5,5,6,6,6,6,6,6,6,7,7,7,7,7,7,7,7};
__device__ const unsigned char CT[NTILES] =
    {0,0,1,0,1,2,0,1,2,3,0,1,2,3,4,0,1,2,3,4,5,0,1,2,3,4,5,6,0,1,2,3,4,5,6,7};

static __device__ __forceinline__ uint smem_u32(const void* p) {
    return (uint)__cvta_generic_to_shared(p);
}
__device__ __forceinline__ void cpasync16(uint dst, const void* src) {
    asm volatile("cp.async.cg.shared.global [%0], [%1], 16;" :: "r"(dst), "l"(src) : "memory");
}
#define CP_COMMIT asm volatile("cp.async.commit_group;" ::: "memory")
#define CP_WAIT1  asm volatile("cp.async.wait_group 1;" ::: "memory")
#define CP_WAIT0  asm volatile("cp.async.wait_group 0;" ::: "memory")

__device__ __forceinline__ void ldsm4(uint* r, uint addr) {
    asm volatile("ldmatrix.sync.aligned.m8n8.x4.shared.b16 {%0,%1,%2,%3}, [%4];"
                 : "=r"(r[0]), "=r"(r[1]), "=r"(r[2]), "=r"(r[3]) : "r"(addr));
}
__device__ __forceinline__ void mma16816(float* c, const uint* a, const uint* b) {
    asm volatile("mma.sync.aligned.m16n8k16.row.col.f32.bf16.bf16.f32 "
        "{%0,%1,%2,%3},{%4,%5,%6,%7},{%8,%9},{%0,%1,%2,%3};"
        : "+f"(c[0]), "+f"(c[1]), "+f"(c[2]), "+f"(c[3])
        : "r"(a[0]), "r"(a[1]), "r"(a[2]), "r"(a[3]), "r"(b[0]), "r"(b[1]));
}
__device__ __forceinline__ void mma16832s8(int* c, const uint* a, const uint* b) {
    asm("mma.sync.aligned.m16n8k32.row.col.s32.s8.s8.s32 "
        "{%0,%1,%2,%3},{%4,%5,%6,%7},{%8,%9},{%0,%1,%2,%3};"
        : "+r"(c[0]), "+r"(c[1]), "+r"(c[2]), "+r"(c[3])
        : "r"(a[0]), "r"(a[1]), "r"(a[2]), "r"(a[3]), "r"(b[0]), "r"(b[1]));
}
__device__ __forceinline__ float clamp127(float v) {
    return fminf(fmaxf(v, -127.0f), 127.0f);
}

// ---------------------------------------------------------------------------
// Kernel 1: M = R*E; store M^T hi/lo and sign-folded M^T hi/lo, [j][d].
// ---------------------------------------------------------------------------
__global__ __launch_bounds__(256) void rot_kernel(const float* __restrict__ E,
                                                  const float* __restrict__ theta) {
    __shared__ float sm[8 * 1028];
    const int tid = threadIdx.x;
    const int j0 = blockIdx.x * 8;

    float ct[NQ], st[NQ];
#pragma unroll
    for (int i = 0; i < NQ; i++) sincosf(0.5f * theta[i], &st[i], &ct[i]);

    for (int idx = tid; idx < 8192; idx += 256) {
        int c = idx & 7, d = idx >> 3;
        sm[c * 1028 + d] = E[d * DIM + j0 + c];
    }
    __syncthreads();

    for (int i = 0; i < NQ; i++) {
        const int m = 9 - i;
        for (int t = tid; t < 4096; t += 256) {
            int c = t >> 9, p = t & 511;
            int low = p & ((1 << m) - 1);
            int d0 = ((p >> m) << (m + 1)) | low;
            int d1 = d0 | (1 << m);
            float a0 = sm[c * 1028 + d0];
            float a1 = sm[c * 1028 + d1];
            sm[c * 1028 + d0] = ct[i] * a0 - st[i] * a1;
            sm[c * 1028 + d1] = st[i] * a0 + ct[i] * a1;
        }
        __syncthreads();
    }

    for (int idx = tid; idx < 8192; idx += 256) {
        int d = idx & 1023, c = idx >> 10;
        float v = sm[c * 1028 + d];
        size_t o = (size_t)(j0 + c) * DIM + d;
        __nv_bfloat16 h = __float2bfloat16(v);
        g_Mth[o] = h;
        g_Mtl[o] = __float2bfloat16(v - __bfloat162float(h));
        float vs = (d < 512) ? v : -v;
        __nv_bfloat16 hs = __float2bfloat16(vs);
        g_Msh[o] = hs;
        g_Msl[o] = __float2bfloat16(vs - __bfloat162float(hs));
    }
}

// ---------------------------------------------------------------------------
// Kernel 2: s-state int8 limbs (radix 256, scale 127) + int16 copy (x32767).
// ---------------------------------------------------------------------------
__global__ __launch_bounds__(128) void state_kernel(const float* __restrict__ x) {
    const int tid = threadIdx.x, lane = tid & 31;
    const int n = blockIdx.x * 4 + (tid >> 5);
    float phi_u = 0.0f, plo_u = 0.0f;
    if (n < NWIN) {
        const int b = n / NWPB;
        const int pos = n - b * NWPB;
        float cs[2][5], sn[2][5];
#pragma unroll
        for (int c = 0; c < 2; c++)
#pragma unroll
            for (int k = 0; k < 5; k++) {
                float v = x[((b * 2 + c) << 12) + pos + k];
                sincosf(0.5f * v, &sn[c][k], &cs[c][k]);
            }
        phi_u = 1.0f; plo_u = 1.0f;
#pragma unroll
        for (int i = 0; i < 5; i++) {
            int bit = (lane >> (4 - i)) & 1;
            phi_u *= bit ? sn[0][i] : cs[0][i];
            plo_u *= bit ? sn[1][i] : cs[1][i];
        }
    }
    char*  Aa = g_Aa + (size_t)n * DIM;
    char*  Ab = g_Ab + (size_t)n * DIM;
    short* Sw = g_Sw + (size_t)n * DIM;
#pragma unroll 4
    for (int rep = 0; rep < 32; rep++) {
        float ph = __shfl_sync(0xffffffffu, phi_u, rep);
        float s = ph * plo_u;
        float s127 = s * 127.0f;
        float a1 = clamp127(rintf(s127));
        float a2 = clamp127(rintf((s127 - a1) * 256.0f));
        Aa[rep * 32 + lane] = (char)(int)a1;
        Ab[rep * 32 + lane] = (char)(int)a2;
        float sw = fminf(fmaxf(rintf(s * 32767.0f), -32767.0f), 32767.0f);
        Sw[rep * 32 + lane] = (short)(int)sw;
    }
}

// ---------------------------------------------------------------------------
// bf16 GEMM-stage machinery (qprep only, 256 threads).
// ---------------------------------------------------------------------------
#define STG 65536
#define ZSM_OFF (3 * STG)
#define SMEM_BYTES (3 * STG + 512)

__device__ __forceinline__ void load_stage_bf16(uint sb, int buf, int tid,
                                                const __nv_bfloat16* aHp, const __nv_bfloat16* aLp,
                                                const __nv_bfloat16* bHp, const __nv_bfloat16* bLp,
                                                size_t aRow0, size_t bRow0, int kElem) {
    const int row = tid >> 1;
    const int cb = (tid & 1) * 4;
    const int r7 = row & 7;
    const uint dbase = sb + (uint)buf * STG + (uint)row * 128;
    const char* aH = (const char*)(aHp + aRow0 + (size_t)row * DIM + kElem);
    const char* aL = (const char*)(aLp + aRow0 + (size_t)row * DIM + kElem);
    const char* bH = (const char*)(bHp + bRow0 + (size_t)row * DIM + kElem);
    const char* bL = (const char*)(bLp + bRow0 + (size_t)row * DIM + kElem);
#pragma unroll
    for (int cc = 0; cc < 4; cc++) {
        int c = cb + cc;
        uint sw = (uint)((c ^ r7) << 4);
        cpasync16(dbase + sw,         aH + c * 16);
        cpasync16(dbase + 16384 + sw, aL + c * 16);
        cpasync16(dbase + 32768 + sw, bH + c * 16);
        cpasync16(dbase + 49152 + sw, bL + c * 16);
    }
    CP_COMMIT;
}

__device__ __forceinline__ void gemm_stage_bf16(uint sb, int buf, int arow0, int ahi,
                                                const int* nrow, int bhi, float* acc) {
    const uint abase = sb + (uint)buf * STG;
    const uint bbase = abase + 32768;
#pragma unroll
    for (int ks = 0; ks < 4; ks++) {
        uint ah[8], al[8], bh[16], bl[16];
#pragma unroll
        for (int i = 0; i < 2; i++) {
            int row = arow0 + 16 * i;
            uint off = (uint)row * 128 + (uint)(((ks * 2 + ahi) ^ (row & 7)) << 4);
            ldsm4(&ah[i * 4], abase + off);
            ldsm4(&al[i * 4], abase + 16384 + off);
        }
#pragma unroll
        for (int jj = 0; jj < 4; jj++) {
            uint off = (uint)nrow[jj] * 128 + (uint)(((ks * 2 + bhi) ^ (nrow[jj] & 7)) << 4);
            ldsm4(&bh[jj * 4], bbase + off);
            ldsm4(&bl[jj * 4], bbase + 16384 + off);
        }
#pragma unroll
        for (int i = 0; i < 2; i++)
#pragma unroll
            for (int j = 0; j < 8; j++) {
                float* c = &acc[(i * 8 + j) * 4];
                mma16816(c, &ah[i * 4], &bh[j * 2]);
                mma16816(c, &ah[i * 4], &bl[j * 2]);
                mma16816(c, &al[i * 4], &bh[j * 2]);
            }
    }
}

// ---------------------------------------------------------------------------
// Kernel 3: Q = M^T Sigma M -> folded int8 limbs (radix 256, scale 127).
// ---------------------------------------------------------------------------
__global__ __launch_bounds__(256, 1) void qprep_kernel() {
    extern __shared__ __align__(128) char smem[];
    const uint sb = smem_u32(smem);
    const int tid = threadIdx.x, lane = tid & 31, wid = tid >> 5;
    const int warp_m = wid & 3, warp_n = wid >> 2;
    const int r = RT[blockIdx.x], c = CT[blockIdx.x];
    const size_t aRow0 = (size_t)r * 128 * DIM;
    const size_t bRow0 = (size_t)c * 128 * DIM;

    const int arow0 = warp_m * 32 + (lane & 15);
    const int ahi = lane >> 4;
    int nrow[4];
#pragma unroll
    for (int jj = 0; jj < 4; jj++)
        nrow[jj] = warp_n * 64 + jj * 16 + ((lane >> 4) & 1) * 8 + (lane & 7);
    const int bhi = (lane >> 3) & 1;

    float acc[64];
#pragma unroll
    for (int i = 0; i < 64; i++) acc[i] = 0.0f;

    load_stage_bf16(sb, 0, tid, g_Mth, g_Mtl, g_Msh, g_Msl, aRow0, bRow0, 0);
    load_stage_bf16(sb, 1, tid, g_Mth, g_Mtl, g_Msh, g_Msl, aRow0, bRow0, 64);

    for (int s = 0; s < 16; s++) {
        if (s < 14) CP_WAIT1; else CP_WAIT0;
        __syncthreads();
        if (s + 2 < 16)
            load_stage_bf16(sb, (s + 2) % 3, tid, g_Mth, g_Mtl, g_Msh, g_Msl,
                            aRow0, bRow0, (s + 2) * 64);
        gemm_stage_bf16(sb, s % 3, arow0, ahi, nrow, bhi, acc);
        __syncthreads();
    }

    const float scale = (r == c) ? 1.0f : 2.0f;
#pragma unroll
    for (int i = 0; i < 2; i++)
#pragma unroll
        for (int j = 0; j < 8; j++) {
            float* cc = &acc[(i * 8 + j) * 4];
            int orow = r * 128 + warp_m * 32 + i * 16 + (lane >> 2);
            int ocol = c * 128 + warp_n * 64 + j * 8 + (lane & 3) * 2;
#pragma unroll
            for (int h = 0; h < 2; h++) {
                int rr = orow + h * 8;
#pragma unroll
                for (int e = 0; e < 2; e++) {
                    float q127 = cc[h * 2 + e] * scale * 127.0f;
                    float b1 = clamp127(rintf(q127));
                    float b2 = clamp127(rintf((q127 - b1) * 256.0f));
                    size_t o = (size_t)rr * DIM + ocol + e;
                    g_Qa[o] = (char)(int)b1;
                    g_Qb[o] = (char)(int)b2;
                }
            }
        }
}

// ---------------------------------------------------------------------------
// Kernel 4: exact int8 limb GEMM with ROW-ACCUMULATED drains (R16 base).
// mma emission reordered in jh-PAIRS so same-accumulator RAW distance is 4
// (>= mma latency at rt8) instead of 1. Otherwise byte-identical to R16.
// ---------------------------------------------------------------------------
__device__ __forceinline__ void load_stage_s8(uint sb, int s, int n0, int tid) {
    const int r = RT[s], c = CT[s];
    const int row = tid >> 1;
    const int cb = (tid & 1) * 4;
    const int r7 = row & 7;
    const uint dbase = sb + (uint)(s % 3) * STG + (uint)row * 128;
    const char* a1 = g_Aa + (size_t)(n0 + row) * DIM + c * 128;
    const char* a2 = g_Ab + (size_t)(n0 + row) * DIM + c * 128;
    const char* b1 = g_Qa + (size_t)(r * 128 + row) * DIM + c * 128;
    const char* b2 = g_Qb + (size_t)(r * 128 + row) * DIM + c * 128;
#pragma unroll
    for (int cc = 0; cc < 4; cc++) {
        int ch = cb + cc;
        uint sw = (uint)((ch ^ r7) << 4);
        cpasync16(dbase + sw,         a1 + ch * 16);
        cpasync16(dbase + 16384 + sw, a2 + ch * 16);
        cpasync16(dbase + 32768 + sw, b1 + ch * 16);
        cpasync16(dbase + 49152 + sw, b2 + ch * 16);
    }
    CP_COMMIT;
}

__global__ __launch_bounds__(256, 1) void qmma_kernel(float* __restrict__ out) {
    extern __shared__ __align__(128) char smem[];
    const uint sb = smem_u32(smem);
    const int tid = threadIdx.x, lane = tid & 31, wid = tid >> 5;
    const int warp_m = wid & 3, warp_n = wid >> 2;
    const int n0 = blockIdx.x * 128;
    float* zsm = (float*)(smem + ZSM_OFF);
    if (tid < 128) zsm[tid] = 0.0f;

    const int arow0 = warp_m * 32 + (lane & 15);
    const int ahi = lane >> 4;
    int nrow[4];
#pragma unroll
    for (int jj = 0; jj < 4; jj++)
        nrow[jj] = warp_n * 64 + jj * 16 + ((lane >> 4) & 1) * 8 + (lane & 7);
    const int bhi = (lane >> 3) & 1;

    const float K1 = 1.0f / (16129.0f * 32767.0f);
    const float K2 = K1 / 256.0f;
    const float K3 = K1 / 65536.0f;

    int i11[64], imd[64], i22[64];
    float zp[4] = {0.0f, 0.0f, 0.0f, 0.0f};
#pragma unroll
    for (int i = 0; i < 64; i++) { i11[i] = 0; imd[i] = 0; i22[i] = 0; }

    load_stage_s8(sb, 0, n0, tid);
    load_stage_s8(sb, 1, n0, tid);

    for (int s = 0; s < NTILES; s++) {
        if (s < NTILES - 2) CP_WAIT1; else CP_WAIT0;
        __syncthreads();
        if (s + 2 < NTILES) load_stage_s8(sb, s + 2, n0, tid);

        const uint A1 = sb + (uint)(s % 3) * STG;
        const uint A2 = A1 + 16384, B1 = A1 + 32768, B2 = A1 + 49152;

        // ---- single combined pass; jh-paired emission (RAW distance 4) ----
#pragma unroll
        for (int ks = 0; ks < 4; ks++) {
            uint a1f[8], a2f[8], b1f[16], b2f[16];
#pragma unroll
            for (int i = 0; i < 2; i++) {
                int row = arow0 + 16 * i;
                uint off = (uint)row * 128 + (uint)(((ks * 2 + ahi) ^ (row & 7)) << 4);
                ldsm4(&a1f[i * 4], A1 + off);
                ldsm4(&a2f[i * 4], A2 + off);
            }
#pragma unroll
            for (int jj = 0; jj < 4; jj++) {
                uint off = (uint)nrow[jj] * 128 + (uint)(((ks * 2 + bhi) ^ (nrow[jj] & 7)) << 4);
                ldsm4(&b1f[jj * 4], B1 + off);
                ldsm4(&b2f[jj * 4], B2 + off);
            }
#pragma unroll
            for (int i = 0; i < 2; i++)
#pragma unroll
                for (int jj = 0; jj < 4; jj++) {
                    const int q0 = (i * 8 + jj * 2) * 4;      // jh = 0
                    const int q1 = q0 + 4;                    // jh = 1
                    const uint* a1p = &a1f[i * 4];
                    const uint* a2p = &a2f[i * 4];
                    const uint* b1p0 = &b1f[jj * 4];
                    const uint* b1p1 = &b1f[jj * 4 + 2];
                    const uint* b2p0 = &b2f[jj * 4];
                    const uint* b2p1 = &b2f[jj * 4 + 2];
                    mma16832s8(&i11[q0], a1p, b1p0);
                    mma16832s8(&i11[q1], a1p, b1p1);
                    mma16832s8(&imd[q0], a1p, b2p0);
                    mma16832s8(&imd[q1], a1p, b2p1);
                    mma16832s8(&i22[q0], a2p, b2p0);
                    mma16832s8(&i22[q1], a2p, b2p1);
                    mma16832s8(&imd[q0], a2p, b1p0);   // RAW dist 4 from imd[q0]
                    mma16832s8(&imd[q1], a2p, b1p1);   // RAW dist 4 from imd[q1]
                }
        }

        // ---- drain once per row (diagonal tile: c == r) -------------------
        if (RT[s] == CT[s]) {
            const int colb = RT[s] * 128 + warp_n * 64 + (lane & 3) * 2;
#pragma unroll
            for (int i = 0; i < 2; i++) {
                const int rg = warp_m * 32 + i * 16 + (lane >> 2);
                const short* w0p = g_Sw + (size_t)(n0 + rg) * DIM + colb;
                const short* w1p = g_Sw + (size_t)(n0 + rg + 8) * DIM + colb;
#pragma unroll
                for (int j = 0; j < 8; j++) {
                    int idx = (i * 8 + j) * 4;
                    short2 sw0 = __ldg((const short2*)(w0p + j * 8));
                    short2 sw1 = __ldg((const short2*)(w1p + j * 8));
                    float t0 = fmaf((float)i22[idx + 0], K3,
                               fmaf((float)imd[idx + 0], K2, (float)i11[idx + 0] * K1));
                    float t1 = fmaf((float)i22[idx + 1], K3,
                               fmaf((float)imd[idx + 1], K2, (float)i11[idx + 1] * K1));
                    float t2 = fmaf((float)i22[idx + 2], K3,
                               fmaf((float)imd[idx + 2], K2, (float)i11[idx + 2] * K1));
                    float t3 = fmaf((float)i22[idx + 3], K3,
                               fmaf((float)imd[idx + 3], K2, (float)i11[idx + 3] * K1));
                    zp[i * 2]     = fmaf((float)sw0.x, t0, fmaf((float)sw0.y, t1, zp[i * 2]));
                    zp[i * 2 + 1] = fmaf((float)sw1.x, t2, fmaf((float)sw1.y, t3, zp[i * 2 + 1]));
                    i11[idx + 0] = 0; i11[idx + 1] = 0; i11[idx + 2] = 0; i11[idx + 3] = 0;
                    imd[idx + 0] = 0; imd[idx + 1] = 0; imd[idx + 2] = 0; imd[idx + 3] = 0;
                    i22[idx + 0] = 0; i22[idx + 1] = 0; i22[idx + 2] = 0; i22[idx + 3] = 0;
                }
            }
        }
    }

    // ---- final reduction (once) ------------------------------------------
#pragma unroll
    for (int q = 0; q < 4; q++) {
        zp[q] += __shfl_xor_sync(0xffffffffu, zp[q], 1);
        zp[q] += __shfl_xor_sync(0xffffffffu, zp[q], 2);
    }
    if ((lane & 3) == 0) {
        const int rbase = warp_m * 32 + (lane >> 2);
        atomicAdd(&zsm[rbase],      zp[0]);
        atomicAdd(&zsm[rbase + 8],  zp[1]);
        atomicAdd(&zsm[rbase + 16], zp[2]);
        atomicAdd(&zsm[rbase + 24], zp[3]);
    }

    __syncthreads();
    if (tid < 128) {
        int n = n0 + tid;
        if (n < NWIN) out[n] = zsm[tid];
    }
}

// ---------------------------------------------------------------------------
extern "C" void kernel_launch(void* const* d_in, const int* in_sizes, int n_in,
                              void* d_out, int out_size) {
    const float* x     = (const float*)d_in[0];
    const float* E     = (const float*)d_in[1];
    const float* theta = (const float*)d_in[2];
    float* out = (float*)d_out;

    rot_kernel<<<DIM / 8, 256>>>(E, theta);
    state_kernel<<<NPAD / 4, 128>>>(x);

    cudaFuncSetAttribute(qprep_kernel,
                         cudaFuncAttributeMaxDynamicSharedMemorySize, SMEM_BYTES);
    qprep_kernel<<<NTILES, 256, SMEM_BYTES>>>();

    cudaFuncSetAttribute(qmma_kernel,
                         cudaFuncAttributeMaxDynamicSharedMemorySize, SMEM_BYTES);
    qmma_kernel<<<NPAD / 128, 256, SMEM_BYTES>>>(out);
}